// round 16
// baseline (speedup 1.0000x reference)
#include <cuda_runtime.h>
#include <cuda_bf16.h>
#include <cstdint>
#include <cstddef>

#define B_  8
#define T_  2048
#define D_  512

#define BM  128
#define BN  128
#define BK  32
#define BKP 40      // padded k-stride (bf16 elems) = 80B rows -> conflict-free fragment LDS
#define NT  256

typedef __nv_bfloat16 BF;

// ---------------------------------------------------------------------------
// Scratch (__device__ globals: allocation-free rule)
// ---------------------------------------------------------------------------
__device__ BF g_QPh[B_*T_*D_], g_QPl[B_*T_*D_];
__device__ BF g_KPh[B_*T_*D_], g_KPl[B_*T_*D_];
__device__ BF g_VTh[B_*T_*D_], g_VTl[B_*T_*D_];            // V projected, [b][d][t]
__device__ float g_S[(size_t)B_*T_*T_];                    // masked scaled scores
__device__ BF g_Ph[(size_t)B_*T_*T_], g_Pl[(size_t)B_*T_*T_]; // softmax probs, split

// ---------------------------------------------------------------------------
// Helpers
// ---------------------------------------------------------------------------
__device__ __forceinline__ uint32_t pack2(BF a, BF b) {
    uint32_t u;
    asm("mov.b32 %0, {%1,%2};" : "=r"(u)
        : "h"(__bfloat16_as_ushort(a)), "h"(__bfloat16_as_ushort(b)));
    return u;
}

__device__ __forceinline__ void split1(float x, BF& h, BF& l) {
    h = __float2bfloat16_rn(x);
    l = __float2bfloat16_rn(x - __bfloat162float(h));
}

// store float4 as 4 hi-bf16 + 4 lo-bf16 (uint2 each)
__device__ __forceinline__ void store_split4(BF* ph, BF* pl, float4 v) {
    BF h0,l0,h1,l1,h2,l2,h3,l3;
    split1(v.x,h0,l0); split1(v.y,h1,l1); split1(v.z,h2,l2); split1(v.w,h3,l3);
    uint2 uh; uh.x = pack2(h0,h1); uh.y = pack2(h2,h3);
    uint2 ul; ul.x = pack2(l0,l1); ul.y = pack2(l2,l3);
    *(uint2*)ph = uh;
    *(uint2*)pl = ul;
}

__device__ __forceinline__ void mma_bf16(float4& d, const uint32_t* a, const uint32_t* b) {
    asm volatile(
        "mma.sync.aligned.m16n8k16.row.col.f32.bf16.bf16.f32 "
        "{%0,%1,%2,%3}, {%4,%5,%6,%7}, {%8,%9}, {%0,%1,%2,%3};\n"
        : "+f"(d.x), "+f"(d.y), "+f"(d.z), "+f"(d.w)
        : "r"(a[0]), "r"(a[1]), "r"(a[2]), "r"(a[3]), "r"(b[0]), "r"(b[1]));
}

// ---------------------------------------------------------------------------
// Shared mainloop step: consumes one BK=32 tile (As/Bs in [row][k] bf16, split).
// Computes hi*hi + hi*lo + lo*hi  (lo*lo dropped, ~2^-18).
// Warp tile 64x32: 4 m-tiles (16) x 4 n-tiles (8).
// ---------------------------------------------------------------------------
__device__ __forceinline__ void mma_step(
    const BF* __restrict__ Ah, const BF* __restrict__ Al,
    const BF* __restrict__ Bh, const BF* __restrict__ Bl,
    int mw, int nw, int g, int tg, float4 acc[4][4])
{
#pragma unroll
    for (int ks = 0; ks < BK; ks += 16) {
        uint32_t af[4][4], bh[4][2], bl[4][2];
#pragma unroll
        for (int mt = 0; mt < 4; mt++) {
            const BF* p = Ah + (mw + mt*16 + g) * BKP + ks + 2*tg;
            af[mt][0] = *(const uint32_t*)(p);
            af[mt][1] = *(const uint32_t*)(p + 8*BKP);
            af[mt][2] = *(const uint32_t*)(p + 8);
            af[mt][3] = *(const uint32_t*)(p + 8*BKP + 8);
        }
#pragma unroll
        for (int nt = 0; nt < 4; nt++) {
            const BF* p = Bh + (nw + nt*8 + g) * BKP + ks + 2*tg;
            bh[nt][0] = *(const uint32_t*)(p);
            bh[nt][1] = *(const uint32_t*)(p + 8);
            const BF* q = Bl + (nw + nt*8 + g) * BKP + ks + 2*tg;
            bl[nt][0] = *(const uint32_t*)(q);
            bl[nt][1] = *(const uint32_t*)(q + 8);
        }
#pragma unroll
        for (int mt = 0; mt < 4; mt++)
#pragma unroll
            for (int nt = 0; nt < 4; nt++)
                mma_bf16(acc[mt][nt], af[mt], bh[nt]);       // hi*hi
#pragma unroll
        for (int mt = 0; mt < 4; mt++)
#pragma unroll
            for (int nt = 0; nt < 4; nt++)
                mma_bf16(acc[mt][nt], af[mt], bl[nt]);       // hi*lo
#pragma unroll
        for (int mt = 0; mt < 4; mt++) {                     // reload A as lo
            const BF* p = Al + (mw + mt*16 + g) * BKP + ks + 2*tg;
            af[mt][0] = *(const uint32_t*)(p);
            af[mt][1] = *(const uint32_t*)(p + 8*BKP);
            af[mt][2] = *(const uint32_t*)(p + 8);
            af[mt][3] = *(const uint32_t*)(p + 8*BKP + 8);
        }
#pragma unroll
        for (int mt = 0; mt < 4; mt++)
#pragma unroll
            for (int nt = 0; nt < 4; nt++)
                mma_bf16(acc[mt][nt], af[mt], bh[nt]);       // lo*hi
    }
}

// ---------------------------------------------------------------------------
// Projection: C[m,n] = sum_k X[m,k]*W[n,k] + bias[n];  M=B*T, N=K=512.
// which: 0 -> QP split, 1 -> KP split, 2 -> VP split TRANSPOSED to [b][d][t]
// ---------------------------------------------------------------------------
__global__ __launch_bounds__(NT, 2) void proj_kernel(
    const float* __restrict__ X, const float* __restrict__ W,
    const float* __restrict__ bias, int which)
{
    const int K = D_, N = D_;
    __shared__ __align__(16) BF As_h[BM][BKP], As_l[BM][BKP];
    __shared__ __align__(16) BF Bs_h[BN][BKP], Bs_l[BN][BKP];

    const int tid = threadIdx.x;
    const int bm = blockIdx.x * BM, bn = blockIdx.y * BN;
    const int warp = tid >> 5, lane = tid & 31;
    const int mw = (warp & 1) * 64, nw = (warp >> 1) * 32;
    const int g = lane >> 2, tg = lane & 3;

    float4 acc[4][4];
#pragma unroll
    for (int i = 0; i < 4; i++)
#pragma unroll
        for (int j = 0; j < 4; j++) acc[i][j] = make_float4(0.f, 0.f, 0.f, 0.f);

    const float* Ag = X + (size_t)bm * K;
    const float* Bg = W + (size_t)bn * K;

    for (int k0 = 0; k0 < K; k0 += BK) {
#pragma unroll
        for (int i = 0; i < 4; i++) {
            int idx = tid + i * NT;
            int r = idx >> 3, c = (idx & 7) << 2;
            float4 a = *(const float4*)(Ag + (size_t)r * K + k0 + c);
            store_split4(&As_h[r][c], &As_l[r][c], a);
            float4 b = *(const float4*)(Bg + (size_t)r * K + k0 + c);
            store_split4(&Bs_h[r][c], &Bs_l[r][c], b);
        }
        __syncthreads();
        mma_step(&As_h[0][0], &As_l[0][0], &Bs_h[0][0], &Bs_l[0][0], mw, nw, g, tg, acc);
        __syncthreads();
    }

    BF* Ch = (which == 0) ? g_QPh : g_KPh;
    BF* Cl = (which == 0) ? g_QPl : g_KPl;

#pragma unroll
    for (int mt = 0; mt < 4; mt++)
#pragma unroll
        for (int nt = 0; nt < 4; nt++) {
            int m = bm + mw + mt * 16 + g;
            int n = bn + nw + nt * 8 + tg * 2;
            float2 bz = *(const float2*)(bias + n);
            float v0 = acc[mt][nt].x + bz.x, v1 = acc[mt][nt].y + bz.y;
            float v2 = acc[mt][nt].z + bz.x, v3 = acc[mt][nt].w + bz.y;
            BF h0,l0,h1,l1,h2,l2,h3,l3;
            split1(v0,h0,l0); split1(v1,h1,l1); split1(v2,h2,l2); split1(v3,h3,l3);
            if (which < 2) {
                *(uint32_t*)(Ch + (size_t)m * N + n)       = pack2(h0, h1);
                *(uint32_t*)(Cl + (size_t)m * N + n)       = pack2(l0, l1);
                *(uint32_t*)(Ch + (size_t)(m + 8) * N + n) = pack2(h2, h3);
                *(uint32_t*)(Cl + (size_t)(m + 8) * N + n) = pack2(l2, l3);
            } else {
                int b = m >> 11, t = m & (T_ - 1);
                size_t base = (size_t)b * D_ * T_;
                g_VTh[base + (size_t)n       * T_ + t]     = h0;
                g_VTl[base + (size_t)n       * T_ + t]     = l0;
                g_VTh[base + (size_t)(n + 1) * T_ + t]     = h1;
                g_VTl[base + (size_t)(n + 1) * T_ + t]     = l1;
                g_VTh[base + (size_t)n       * T_ + t + 8] = h2;
                g_VTl[base + (size_t)n       * T_ + t + 8] = l2;
                g_VTh[base + (size_t)(n + 1) * T_ + t + 8] = h3;
                g_VTl[base + (size_t)(n + 1) * T_ + t + 8] = l3;
            }
        }
}

// ---------------------------------------------------------------------------
// Scores: S[b,m,n] = (QP[b,m,:] . KP[b,n,:]) * scale * mask[b,m,n]
// ---------------------------------------------------------------------------
__global__ __launch_bounds__(NT, 2) void score_kernel(const float* __restrict__ mask)
{
    const int K = D_, N = T_;
    const float scale = 0.04419417382415922f;  // 1/sqrt(512)

    const int b = blockIdx.z;
    const BF* Agh = g_QPh + (size_t)b * T_ * D_ + (size_t)blockIdx.x * BM * K;
    const BF* Agl = g_QPl + (size_t)b * T_ * D_ + (size_t)blockIdx.x * BM * K;
    const BF* Bgh = g_KPh + (size_t)b * T_ * D_ + (size_t)blockIdx.y * BN * K;
    const BF* Bgl = g_KPl + (size_t)b * T_ * D_ + (size_t)blockIdx.y * BN * K;
    const float* Mg = mask + (size_t)b * T_ * T_;
    float*       Cg = g_S  + (size_t)b * T_ * T_;

    __shared__ __align__(16) BF As_h[BM][BKP], As_l[BM][BKP];
    __shared__ __align__(16) BF Bs_h[BN][BKP], Bs_l[BN][BKP];

    const int tid = threadIdx.x;
    const int warp = tid >> 5, lane = tid & 31;
    const int mw = (warp & 1) * 64, nw = (warp >> 1) * 32;
    const int g = lane >> 2, tg = lane & 3;

    float4 acc[4][4];
#pragma unroll
    for (int i = 0; i < 4; i++)
#pragma unroll
        for (int j = 0; j < 4; j++) acc[i][j] = make_float4(0.f, 0.f, 0.f, 0.f);

    for (int k0 = 0; k0 < K; k0 += BK) {
#pragma unroll
        for (int i = 0; i < 4; i++) {
            int idx = tid + i * NT;
            int r = idx >> 3, c = (idx & 7) << 2;
            *(uint2*)&As_h[r][c] = *(const uint2*)(Agh + (size_t)r * K + k0 + c);
            *(uint2*)&As_l[r][c] = *(const uint2*)(Agl + (size_t)r * K + k0 + c);
            *(uint2*)&Bs_h[r][c] = *(const uint2*)(Bgh + (size_t)r * K + k0 + c);
            *(uint2*)&Bs_l[r][c] = *(const uint2*)(Bgl + (size_t)r * K + k0 + c);
        }
        __syncthreads();
        mma_step(&As_h[0][0], &As_l[0][0], &Bs_h[0][0], &Bs_l[0][0], mw, nw, g, tg, acc);
        __syncthreads();
    }

    const int bm = blockIdx.x * BM, bn = blockIdx.y * BN;
#pragma unroll
    for (int mt = 0; mt < 4; mt++)
#pragma unroll
        for (int nt = 0; nt < 4; nt++) {
            int m = bm + mw + mt * 16 + g;
            int n = bn + nw + nt * 8 + tg * 2;
            float2 mk0 = *(const float2*)(Mg + (size_t)m * N + n);
            float2 mk1 = *(const float2*)(Mg + (size_t)(m + 8) * N + n);
            float2 o0, o1;
            o0.x = acc[mt][nt].x * scale * mk0.x;
            o0.y = acc[mt][nt].y * scale * mk0.y;
            o1.x = acc[mt][nt].z * scale * mk1.x;
            o1.y = acc[mt][nt].w * scale * mk1.y;
            *(float2*)(Cg + (size_t)m * N + n)       = o0;
            *(float2*)(Cg + (size_t)(m + 8) * N + n) = o1;
        }
}

// ---------------------------------------------------------------------------
// Row softmax over g_S; emits P pre-split (bf16 hi/lo). One CTA per row.
// ---------------------------------------------------------------------------
__global__ __launch_bounds__(NT) void softmax_kernel()
{
    const float* p = g_S + (size_t)blockIdx.x * T_;
    const int tid = threadIdx.x;

    float4 a = *(const float4*)(p + tid * 4);
    float4 b = *(const float4*)(p + 1024 + tid * 4);

    float m = fmaxf(fmaxf(fmaxf(a.x, a.y), fmaxf(a.z, a.w)),
                    fmaxf(fmaxf(b.x, b.y), fmaxf(b.z, b.w)));

    __shared__ float red[NT];
    red[tid] = m;
    __syncthreads();
#pragma unroll
    for (int s = NT / 2; s > 0; s >>= 1) {
        if (tid < s) red[tid] = fmaxf(red[tid], red[tid + s]);
        __syncthreads();
    }
    float rowmax = red[0];
    __syncthreads();

    a.x = __expf(a.x - rowmax); a.y = __expf(a.y - rowmax);
    a.z = __expf(a.z - rowmax); a.w = __expf(a.w - rowmax);
    b.x = __expf(b.x - rowmax); b.y = __expf(b.y - rowmax);
    b.z = __expf(b.z - rowmax); b.w = __expf(b.w - rowmax);

    float s8 = (a.x + a.y) + (a.z + a.w) + (b.x + b.y) + (b.z + b.w);
    red[tid] = s8;
    __syncthreads();
#pragma unroll
    for (int s = NT / 2; s > 0; s >>= 1) {
        if (tid < s) red[tid] += red[tid + s];
        __syncthreads();
    }
    float inv = 1.0f / red[0];

    a.x *= inv; a.y *= inv; a.z *= inv; a.w *= inv;
    b.x *= inv; b.y *= inv; b.z *= inv; b.w *= inv;

    size_t row = (size_t)blockIdx.x * T_;
    store_split4(g_Ph + row + tid * 4,        g_Pl + row + tid * 4,        a);
    store_split4(g_Ph + row + 1024 + tid * 4, g_Pl + row + 1024 + tid * 4, b);
}

// ---------------------------------------------------------------------------
// Output: O[b,m,n] = sum_k P[b,m,k] * VT[b,n,k]   (VT is [b][d][t], so NT form)
// ---------------------------------------------------------------------------
__global__ __launch_bounds__(NT, 2) void pv_kernel(float* __restrict__ out)
{
    const int K = T_, N = D_;

    const int b = blockIdx.z;
    const BF* Agh = g_Ph + (size_t)b * T_ * T_ + (size_t)blockIdx.x * BM * K;
    const BF* Agl = g_Pl + (size_t)b * T_ * T_ + (size_t)blockIdx.x * BM * K;
    const BF* Bgh = g_VTh + (size_t)b * D_ * T_ + (size_t)blockIdx.y * BN * K;
    const BF* Bgl = g_VTl + (size_t)b * D_ * T_ + (size_t)blockIdx.y * BN * K;
    float*    Cg  = out   + (size_t)b * T_ * D_;

    __shared__ __align__(16) BF As_h[BM][BKP], As_l[BM][BKP];
    __shared__ __align__(16) BF Bs_h[BN][BKP], Bs_l[BN][BKP];

    const int tid = threadIdx.x;
    const int warp = tid >> 5, lane = tid & 31;
    const int mw = (warp & 1) * 64, nw = (warp >> 1) * 32;
    const int g = lane >> 2, tg = lane & 3;

    float4 acc[4][4];
#pragma unroll
    for (int i = 0; i < 4; i++)
#pragma unroll
        for (int j = 0; j < 4; j++) acc[i][j] = make_float4(0.f, 0.f, 0.f, 0.f);

    for (int k0 = 0; k0 < K; k0 += BK) {
#pragma unroll
        for (int i = 0; i < 4; i++) {
            int idx = tid + i * NT;
            int r = idx >> 3, c = (idx & 7) << 2;
            *(uint2*)&As_h[r][c] = *(const uint2*)(Agh + (size_t)r * K + k0 + c);
            *(uint2*)&As_l[r][c] = *(const uint2*)(Agl + (size_t)r * K + k0 + c);
            *(uint2*)&Bs_h[r][c] = *(const uint2*)(Bgh + (size_t)r * K + k0 + c);
            *(uint2*)&Bs_l[r][c] = *(const uint2*)(Bgl + (size_t)r * K + k0 + c);
        }
        __syncthreads();
        mma_step(&As_h[0][0], &As_l[0][0], &Bs_h[0][0], &Bs_l[0][0], mw, nw, g, tg, acc);
        __syncthreads();
    }

    const int bm = blockIdx.x * BM, bn = blockIdx.y * BN;
#pragma unroll
    for (int mt = 0; mt < 4; mt++)
#pragma unroll
        for (int nt = 0; nt < 4; nt++) {
            int m = bm + mw + mt * 16 + g;
            int n = bn + nw + nt * 8 + tg * 2;
            float2 o0 = make_float2(acc[mt][nt].x, acc[mt][nt].y);
            float2 o1 = make_float2(acc[mt][nt].z, acc[mt][nt].w);
            *(float2*)(Cg + (size_t)m * N + n)       = o0;
            *(float2*)(Cg + (size_t)(m + 8) * N + n) = o1;
        }
}

// ---------------------------------------------------------------------------
// Launch
// ---------------------------------------------------------------------------
extern "C" void kernel_launch(void* const* d_in, const int* in_sizes, int n_in,
                              void* d_out, int out_size)
{
    const float* q    = (const float*)d_in[0];
    const float* k    = (const float*)d_in[1];
    const float* v    = (const float*)d_in[2];
    const float* Wq   = (const float*)d_in[3];
    const float* bq   = (const float*)d_in[4];
    const float* Wk   = (const float*)d_in[5];
    const float* bk   = (const float*)d_in[6];
    const float* Wv   = (const float*)d_in[7];
    const float* bv   = (const float*)d_in[8];
    const float* mask = (const float*)d_in[9];
    float* out = (float*)d_out;

    dim3 gp((B_ * T_) / BM, D_ / BN);
    proj_kernel<<<gp, NT>>>(q, Wq, bq, 0);
    proj_kernel<<<gp, NT>>>(k, Wk, bk, 1);
    proj_kernel<<<gp, NT>>>(v, Wv, bv, 2);

    dim3 gs(T_ / BM, T_ / BN, B_);
    score_kernel<<<gs, NT>>>(mask);

    softmax_kernel<<<B_ * T_, NT>>>();

    dim3 go(T_ / BM, D_ / BN, B_);
    pv_kernel<<<go, NT>>>(out);
}

// round 17
// speedup vs baseline: 1.1964x; 1.1964x over previous
#include <cuda_runtime.h>
#include <cuda_bf16.h>
#include <cstdint>
#include <cstddef>

#define B_  8
#define T_  2048
#define D_  512

#define BM  128
#define BN  128
#define BK  32
#define BKP 40      // padded k-stride (bf16) = 80B rows -> conflict-free LDS/LDSM
#define NT  256

#define ARR  (BM * BKP)          // 5120 elems per array
#define STAGE (4 * ARR)          // Ah, Al, Bh, Bl
#define SMEM_BYTES (2 * STAGE * 2)   // 2 stages * bf16 = 81920 B

typedef __nv_bfloat16 BF;

// ---------------------------------------------------------------------------
// Scratch (__device__ globals: allocation-free rule)
// ---------------------------------------------------------------------------
__device__ __align__(16) BF g_QPh[B_*T_*D_], g_QPl[B_*T_*D_];
__device__ __align__(16) BF g_KPh[B_*T_*D_], g_KPl[B_*T_*D_];
__device__ __align__(16) BF g_VTh[B_*T_*D_], g_VTl[B_*T_*D_];  // V proj, [b][d][t]
__device__ __align__(16) float g_S[(size_t)B_*T_*T_];
__device__ __align__(16) BF g_Ph[(size_t)B_*T_*T_], g_Pl[(size_t)B_*T_*T_];

// ---------------------------------------------------------------------------
// Helpers
// ---------------------------------------------------------------------------
__device__ __forceinline__ uint32_t pack2(BF a, BF b) {
    uint32_t u;
    asm("mov.b32 %0, {%1,%2};" : "=r"(u)
        : "h"(__bfloat16_as_ushort(a)), "h"(__bfloat16_as_ushort(b)));
    return u;
}

__device__ __forceinline__ void split1(float x, BF& h, BF& l) {
    h = __float2bfloat16_rn(x);
    l = __float2bfloat16_rn(x - __bfloat162float(h));
}

__device__ __forceinline__ void store_split4(BF* ph, BF* pl, float4 v) {
    BF h0,l0,h1,l1,h2,l2,h3,l3;
    split1(v.x,h0,l0); split1(v.y,h1,l1); split1(v.z,h2,l2); split1(v.w,h3,l3);
    uint2 uh; uh.x = pack2(h0,h1); uh.y = pack2(h2,h3);
    uint2 ul; ul.x = pack2(l0,l1); ul.y = pack2(l2,l3);
    *(uint2*)ph = uh;
    *(uint2*)pl = ul;
}

__device__ __forceinline__ void mma_bf16(float4& d, const uint32_t* a, const uint32_t* b) {
    asm volatile(
        "mma.sync.aligned.m16n8k16.row.col.f32.bf16.bf16.f32 "
        "{%0,%1,%2,%3}, {%4,%5,%6,%7}, {%8,%9}, {%0,%1,%2,%3};\n"
        : "+f"(d.x), "+f"(d.y), "+f"(d.z), "+f"(d.w)
        : "r"(a[0]), "r"(a[1]), "r"(a[2]), "r"(a[3]), "r"(b[0]), "r"(b[1]));
}

__device__ __forceinline__ void ldsm4(uint32_t& r0, uint32_t& r1, uint32_t& r2, uint32_t& r3,
                                      const BF* p) {
    uint32_t a = (uint32_t)__cvta_generic_to_shared(p);
    asm volatile("ldmatrix.sync.aligned.m8n8.x4.shared.b16 {%0,%1,%2,%3}, [%4];"
                 : "=r"(r0), "=r"(r1), "=r"(r2), "=r"(r3) : "r"(a));
}

__device__ __forceinline__ void cpa16(BF* dst, const BF* src) {
    uint32_t d = (uint32_t)__cvta_generic_to_shared(dst);
    asm volatile("cp.async.cg.shared.global [%0], [%1], 16;" :: "r"(d), "l"(src));
}

// ---------------------------------------------------------------------------
// Mainloop step: one BK=32 tile. hi*hi + hi*lo + lo*hi (lo*lo dropped ~2^-18).
// Warp tile 64x32. Fragments via ldmatrix.x4.
// ---------------------------------------------------------------------------
__device__ __forceinline__ void mma_step(
    const BF* __restrict__ Ah, const BF* __restrict__ Al,
    const BF* __restrict__ Bh, const BF* __restrict__ Bl,
    int mw, int nw, int lane, float4 acc[4][4])
{
    const int lr  = lane & 15;            // A: row within 16
    const int lkh = (lane >> 4) << 3;     // A: k-half select
    const int brow = lane & 7;            // B: row within 8
    const int bn0 = ((lane >> 4) & 1) << 3;   // B: n-tile within pair (quad>>1)
    const int bkh = ((lane >> 3) & 1) << 3;   // B: k-half (quad&1)

#pragma unroll
    for (int ks = 0; ks < BK; ks += 16) {
        uint32_t af[4][4], bh[4][2], bl[4][2];
#pragma unroll
        for (int mt = 0; mt < 4; mt++)
            ldsm4(af[mt][0], af[mt][1], af[mt][2], af[mt][3],
                  Ah + (mw + mt*16 + lr) * BKP + ks + lkh);
        ldsm4(bh[0][0], bh[0][1], bh[1][0], bh[1][1],
              Bh + (nw +      bn0 + brow) * BKP + ks + bkh);
        ldsm4(bh[2][0], bh[2][1], bh[3][0], bh[3][1],
              Bh + (nw + 16 + bn0 + brow) * BKP + ks + bkh);
        ldsm4(bl[0][0], bl[0][1], bl[1][0], bl[1][1],
              Bl + (nw +      bn0 + brow) * BKP + ks + bkh);
        ldsm4(bl[2][0], bl[2][1], bl[3][0], bl[3][1],
              Bl + (nw + 16 + bn0 + brow) * BKP + ks + bkh);

#pragma unroll
        for (int mt = 0; mt < 4; mt++)
#pragma unroll
            for (int nt = 0; nt < 4; nt++)
                mma_bf16(acc[mt][nt], af[mt], bh[nt]);       // hi*hi
#pragma unroll
        for (int mt = 0; mt < 4; mt++)
#pragma unroll
            for (int nt = 0; nt < 4; nt++)
                mma_bf16(acc[mt][nt], af[mt], bl[nt]);       // hi*lo
#pragma unroll
        for (int mt = 0; mt < 4; mt++)                       // reload A as lo
            ldsm4(af[mt][0], af[mt][1], af[mt][2], af[mt][3],
                  Al + (mw + mt*16 + lr) * BKP + ks + lkh);
#pragma unroll
        for (int mt = 0; mt < 4; mt++)
#pragma unroll
            for (int nt = 0; nt < 4; nt++)
                mma_bf16(acc[mt][nt], af[mt], bh[nt]);       // lo*hi
    }
}

// ---------------------------------------------------------------------------
// cp.async stage fill for bf16 GEMMs: 4 arrays x (128 rows x 64B), 16B granules
// ---------------------------------------------------------------------------
__device__ __forceinline__ void stage_fill(
    BF* st, int tid, int kk0,
    const BF* Agh, const BF* Agl, const BF* Bgh, const BF* Bgl, int K)
{
#pragma unroll
    for (int j = 0; j < 2; j++) {
        int idx = tid + j * NT;
        int r = idx >> 2, c8 = (idx & 3) << 3;
        size_t go = (size_t)r * K + kk0 + c8;
        int so = r * BKP + c8;
        cpa16(st +           so, Agh + go);
        cpa16(st +   ARR   + so, Agl + go);
        cpa16(st + 2*ARR   + so, Bgh + go);
        cpa16(st + 3*ARR   + so, Bgl + go);
    }
    asm volatile("cp.async.commit_group;" ::: "memory");
}

// ---------------------------------------------------------------------------
// Projection: C[m,n] = sum_k X[m,k]*W[n,k] + bias[n];  M=B*T, N=K=512.
// which: 0 -> QP split, 1 -> KP split, 2 -> VP split TRANSPOSED to [b][d][t]
// ---------------------------------------------------------------------------
__global__ __launch_bounds__(NT, 2) void proj_kernel(
    const float* __restrict__ X, const float* __restrict__ W,
    const float* __restrict__ bias, int which)
{
    const int K = D_, N = D_;
    __shared__ __align__(16) BF As_h[BM][BKP], As_l[BM][BKP];
    __shared__ __align__(16) BF Bs_h[BN][BKP], Bs_l[BN][BKP];

    const int tid = threadIdx.x;
    const int bm = blockIdx.x * BM, bn = blockIdx.y * BN;
    const int warp = tid >> 5, lane = tid & 31;
    const int mw = (warp & 1) * 64, nw = (warp >> 1) * 32;
    const int g = lane >> 2, tg = lane & 3;

    float4 acc[4][4];
#pragma unroll
    for (int i = 0; i < 4; i++)
#pragma unroll
        for (int j = 0; j < 4; j++) acc[i][j] = make_float4(0.f, 0.f, 0.f, 0.f);

    const float* Ag = X + (size_t)bm * K;
    const float* Bg = W + (size_t)bn * K;

    for (int k0 = 0; k0 < K; k0 += BK) {
#pragma unroll
        for (int i = 0; i < 4; i++) {
            int idx = tid + i * NT;
            int r = idx >> 3, c = (idx & 7) << 2;
            float4 a = *(const float4*)(Ag + (size_t)r * K + k0 + c);
            store_split4(&As_h[r][c], &As_l[r][c], a);
            float4 b = *(const float4*)(Bg + (size_t)r * K + k0 + c);
            store_split4(&Bs_h[r][c], &Bs_l[r][c], b);
        }
        __syncthreads();
        mma_step(&As_h[0][0], &As_l[0][0], &Bs_h[0][0], &Bs_l[0][0], mw, nw, lane, acc);
        __syncthreads();
    }

    BF* Ch = (which == 0) ? g_QPh : g_KPh;
    BF* Cl = (which == 0) ? g_QPl : g_KPl;

#pragma unroll
    for (int mt = 0; mt < 4; mt++)
#pragma unroll
        for (int nt = 0; nt < 4; nt++) {
            int m = bm + mw + mt * 16 + g;
            int n = bn + nw + nt * 8 + tg * 2;
            float2 bz = *(const float2*)(bias + n);
            float v0 = acc[mt][nt].x + bz.x, v1 = acc[mt][nt].y + bz.y;
            float v2 = acc[mt][nt].z + bz.x, v3 = acc[mt][nt].w + bz.y;
            BF h0,l0,h1,l1,h2,l2,h3,l3;
            split1(v0,h0,l0); split1(v1,h1,l1); split1(v2,h2,l2); split1(v3,h3,l3);
            if (which < 2) {
                *(uint32_t*)(Ch + (size_t)m * N + n)       = pack2(h0, h1);
                *(uint32_t*)(Cl + (size_t)m * N + n)       = pack2(l0, l1);
                *(uint32_t*)(Ch + (size_t)(m + 8) * N + n) = pack2(h2, h3);
                *(uint32_t*)(Cl + (size_t)(m + 8) * N + n) = pack2(l2, l3);
            } else {
                int b = m >> 11, t = m & (T_ - 1);
                size_t base = (size_t)b * D_ * T_;
                g_VTh[base + (size_t)n       * T_ + t]     = h0;
                g_VTl[base + (size_t)n       * T_ + t]     = l0;
                g_VTh[base + (size_t)(n + 1) * T_ + t]     = h1;
                g_VTl[base + (size_t)(n + 1) * T_ + t]     = l1;
                g_VTh[base + (size_t)n       * T_ + t + 8] = h2;
                g_VTl[base + (size_t)n       * T_ + t + 8] = l2;
                g_VTh[base + (size_t)(n + 1) * T_ + t + 8] = h3;
                g_VTl[base + (size_t)(n + 1) * T_ + t + 8] = l3;
            }
        }
}

// ---------------------------------------------------------------------------
// Scores: S[b,m,n] = (QP[b,m,:] . KP[b,n,:]) * scale * mask[b,m,n]
// 2-stage cp.async pipeline.
// ---------------------------------------------------------------------------
__global__ __launch_bounds__(NT, 2) void score_kernel(const float* __restrict__ mask)
{
    const int K = D_, N = T_;
    const int KT = K / BK;
    const float scale = 0.04419417382415922f;  // 1/sqrt(512)

    extern __shared__ __align__(16) BF sm[];

    const int b = blockIdx.z;
    const BF* Agh = g_QPh + (size_t)b * T_ * D_ + (size_t)blockIdx.x * BM * K;
    const BF* Agl = g_QPl + (size_t)b * T_ * D_ + (size_t)blockIdx.x * BM * K;
    const BF* Bgh = g_KPh + (size_t)b * T_ * D_ + (size_t)blockIdx.y * BN * K;
    const BF* Bgl = g_KPl + (size_t)b * T_ * D_ + (size_t)blockIdx.y * BN * K;
    const float* Mg = mask + (size_t)b * T_ * T_;
    float*       Cg = g_S  + (size_t)b * T_ * T_;

    const int tid = threadIdx.x;
    const int warp = tid >> 5, lane = tid & 31;
    const int mw = (warp & 1) * 64, nw = (warp >> 1) * 32;
    const int g = lane >> 2, tg = lane & 3;

    float4 acc[4][4];
#pragma unroll
    for (int i = 0; i < 4; i++)
#pragma unroll
        for (int j = 0; j < 4; j++) acc[i][j] = make_float4(0.f, 0.f, 0.f, 0.f);

    stage_fill(sm, tid, 0, Agh, Agl, Bgh, Bgl, K);

    for (int i = 0; i < KT; i++) {
        BF* st = sm + (i & 1) * STAGE;
        if (i + 1 < KT) {
            stage_fill(sm + ((i + 1) & 1) * STAGE, tid, (i + 1) * BK,
                       Agh, Agl, Bgh, Bgl, K);
            asm volatile("cp.async.wait_group 1;" ::: "memory");
        } else {
            asm volatile("cp.async.wait_group 0;" ::: "memory");
        }
        __syncthreads();
        mma_step(st, st + ARR, st + 2*ARR, st + 3*ARR, mw, nw, lane, acc);
        __syncthreads();
    }

    const int bm = blockIdx.x * BM, bn = blockIdx.y * BN;
#pragma unroll
    for (int mt = 0; mt < 4; mt++)
#pragma unroll
        for (int nt = 0; nt < 4; nt++) {
            int m = bm + mw + mt * 16 + g;
            int n = bn + nw + nt * 8 + tg * 2;
            float2 mk0 = *(const float2*)(Mg + (size_t)m * N + n);
            float2 mk1 = *(const float2*)(Mg + (size_t)(m + 8) * N + n);
            float2 o0, o1;
            o0.x = acc[mt][nt].x * scale * mk0.x;
            o0.y = acc[mt][nt].y * scale * mk0.y;
            o1.x = acc[mt][nt].z * scale * mk1.x;
            o1.y = acc[mt][nt].w * scale * mk1.y;
            *(float2*)(Cg + (size_t)m * N + n)       = o0;
            *(float2*)(Cg + (size_t)(m + 8) * N + n) = o1;
        }
}

// ---------------------------------------------------------------------------
// Row softmax over g_S; emits P pre-split (bf16 hi/lo). One CTA per row.
// ---------------------------------------------------------------------------
__global__ __launch_bounds__(NT) void softmax_kernel()
{
    const float* p = g_S + (size_t)blockIdx.x * T_;
    const int tid = threadIdx.x;

    float4 a = *(const float4*)(p + tid * 4);
    float4 b = *(const float4*)(p + 1024 + tid * 4);

    float m = fmaxf(fmaxf(fmaxf(a.x, a.y), fmaxf(a.z, a.w)),
                    fmaxf(fmaxf(b.x, b.y), fmaxf(b.z, b.w)));

    __shared__ float red[NT];
    red[tid] = m;
    __syncthreads();
#pragma unroll
    for (int s = NT / 2; s > 0; s >>= 1) {
        if (tid < s) red[tid] = fmaxf(red[tid], red[tid + s]);
        __syncthreads();
    }
    float rowmax = red[0];
    __syncthreads();

    a.x = __expf(a.x - rowmax); a.y = __expf(a.y - rowmax);
    a.z = __expf(a.z - rowmax); a.w = __expf(a.w - rowmax);
    b.x = __expf(b.x - rowmax); b.y = __expf(b.y - rowmax);
    b.z = __expf(b.z - rowmax); b.w = __expf(b.w - rowmax);

    float s8 = (a.x + a.y) + (a.z + a.w) + (b.x + b.y) + (b.z + b.w);
    red[tid] = s8;
    __syncthreads();
#pragma unroll
    for (int s = NT / 2; s > 0; s >>= 1) {
        if (tid < s) red[tid] += red[tid + s];
        __syncthreads();
    }
    float inv = 1.0f / red[0];

    a.x *= inv; a.y *= inv; a.z *= inv; a.w *= inv;
    b.x *= inv; b.y *= inv; b.z *= inv; b.w *= inv;

    size_t row = (size_t)blockIdx.x * T_;
    store_split4(g_Ph + row + tid * 4,        g_Pl + row + tid * 4,        a);
    store_split4(g_Ph + row + 1024 + tid * 4, g_Pl + row + 1024 + tid * 4, b);
}

// ---------------------------------------------------------------------------
// Output: O[b,m,n] = sum_k P[b,m,k] * VT[b,n,k]   (VT is [b][d][t], NT form)
// 2-stage cp.async pipeline.
// ---------------------------------------------------------------------------
__global__ __launch_bounds__(NT, 2) void pv_kernel(float* __restrict__ out)
{
    const int K = T_, N = D_;
    const int KT = K / BK;

    extern __shared__ __align__(16) BF sm[];

    const int b = blockIdx.z;
    const BF* Agh = g_Ph + (size_t)b * T_ * T_ + (size_t)blockIdx.x * BM * K;
    const BF* Agl = g_Pl + (size_t)b * T_ * T_ + (size_t)blockIdx.x * BM * K;
    const BF* Bgh = g_VTh + (size_t)b * D_ * T_ + (size_t)blockIdx.y * BN * K;
    const BF* Bgl = g_VTl + (size_t)b * D_ * T_ + (size_t)blockIdx.y * BN * K;
    float*    Cg  = out   + (size_t)b * T_ * D_;

    const int tid = threadIdx.x;
    const int warp = tid >> 5, lane = tid & 31;
    const int mw = (warp & 1) * 64, nw = (warp >> 1) * 32;
    const int g = lane >> 2, tg = lane & 3;

    float4 acc[4][4];
#pragma unroll
    for (int i = 0; i < 4; i++)
#pragma unroll
        for (int j = 0; j < 4; j++) acc[i][j] = make_float4(0.f, 0.f, 0.f, 0.f);

    stage_fill(sm, tid, 0, Agh, Agl, Bgh, Bgl, K);

    for (int i = 0; i < KT; i++) {
        BF* st = sm + (i & 1) * STAGE;
        if (i + 1 < KT) {
            stage_fill(sm + ((i + 1) & 1) * STAGE, tid, (i + 1) * BK,
                       Agh, Agl, Bgh, Bgl, K);
            asm volatile("cp.async.wait_group 1;" ::: "memory");
        } else {
            asm volatile("cp.async.wait_group 0;" ::: "memory");
        }
        __syncthreads();
        mma_step(st, st + ARR, st + 2*ARR, st + 3*ARR, mw, nw, lane, acc);
        __syncthreads();
    }

    const int bm = blockIdx.x * BM, bn = blockIdx.y * BN;
#pragma unroll
    for (int mt = 0; mt < 4; mt++)
#pragma unroll
        for (int nt = 0; nt < 4; nt++) {
            int m = bm + mw + mt * 16 + g;
            int n = bn + nw + nt * 8 + tg * 2;
            float2 o0 = make_float2(acc[mt][nt].x, acc[mt][nt].y);
            float2 o1 = make_float2(acc[mt][nt].z, acc[mt][nt].w);
            *(float2*)(Cg + (size_t)m * N + n)       = o0;
            *(float2*)(Cg + (size_t)(m + 8) * N + n) = o1;
        }
}

// ---------------------------------------------------------------------------
// Launch
// ---------------------------------------------------------------------------
extern "C" void kernel_launch(void* const* d_in, const int* in_sizes, int n_in,
                              void* d_out, int out_size)
{
    const float* q    = (const float*)d_in[0];
    const float* k    = (const float*)d_in[1];
    const float* v    = (const float*)d_in[2];
    const float* Wq   = (const float*)d_in[3];
    const float* bq   = (const float*)d_in[4];
    const float* Wk   = (const float*)d_in[5];
    const float* bk   = (const float*)d_in[6];
    const float* Wv   = (const float*)d_in[7];
    const float* bv   = (const float*)d_in[8];
    const float* mask = (const float*)d_in[9];
    float* out = (float*)d_out;

    cudaFuncSetAttribute(score_kernel, cudaFuncAttributeMaxDynamicSharedMemorySize, SMEM_BYTES);
    cudaFuncSetAttribute(pv_kernel,    cudaFuncAttributeMaxDynamicSharedMemorySize, SMEM_BYTES);

    dim3 gp((B_ * T_) / BM, D_ / BN);
    proj_kernel<<<gp, NT>>>(q, Wq, bq, 0);
    proj_kernel<<<gp, NT>>>(k, Wk, bk, 1);
    proj_kernel<<<gp, NT>>>(v, Wv, bv, 2);

    dim3 gs(T_ / BM, T_ / BN, B_);
    score_kernel<<<gs, NT, SMEM_BYTES>>>(mask);

    softmax_kernel<<<B_ * T_, NT>>>();

    dim3 go(T_ / BM, D_ / BN, B_);
    pv_kernel<<<go, NT, SMEM_BYTES>>>(out);
}